// round 4
// baseline (speedup 1.0000x reference)
#include <cuda_runtime.h>
#include <cuda_fp16.h>

#define NN 100000
#define NE 1600000
#define NCHUNK 4
#define CHN 25000          // nodes per chunk (NN / NCHUNK)

// xw chunk scratch in fp16: [CHN][25 kernels][32 feats] = 1600B/node = 40 MB
__device__ uint2 g_xwh[(size_t)CHN * 200];
__device__ float g_acc[(size_t)NN * 32];
__device__ float g_xrb[(size_t)NN * 32];
__device__ float g_rdot[NN];
__device__ float g_denom[NN];

typedef unsigned long long u64;

__device__ __forceinline__ u64 pack2(float a, float b) {
    u64 r; asm("mov.b64 %0,{%1,%2};" : "=l"(r) : "f"(a), "f"(b)); return r;
}
__device__ __forceinline__ void unpack2(u64 v, float& a, float& b) {
    asm("mov.b64 {%0,%1},%2;" : "=f"(a), "=f"(b) : "l"(v));
}
// packed fp32x2 FMA — 2x scalar FFMA throughput on sm_103a
__device__ __forceinline__ u64 fma2(u64 a, u64 b, u64 c) {
    u64 d; asm("fma.rn.f32x2 %0,%1,%2,%3;" : "=l"(d) : "l"(a), "l"(b), "l"(c)); return d;
}
// fp32 pair -> packed half2 bits
__device__ __forceinline__ unsigned h2bits(u64 v) {
    float a, b; unpack2(v, a, b);
    unsigned r; asm("cvt.rn.f16x2.f32 %0,%2,%1;" : "=r"(r) : "f"(a), "f"(b));
    return r;
}

// ---------------------------------------------------------------------------
// K1: per-node root transform + attention dot + zero-init of accumulators
// ---------------------------------------------------------------------------
__global__ __launch_bounds__(256) void k1_node(
    const float* __restrict__ x, const float* __restrict__ rootW,
    const float* __restrict__ attW, const float* __restrict__ bias)
{
    __shared__ __align__(16) float Rs[1024];
    __shared__ float a1s[32], bsh[32];
    int tid = threadIdx.x;
    ((float4*)Rs)[tid] = ((const float4*)rootW)[tid];
    if (tid < 32) { a1s[tid] = attW[tid]; bsh[tid] = bias[tid]; }
    __syncthreads();

    int n = blockIdx.x * 256 + tid;
    if (n >= NN) return;

    float xv[32];
    const float4* xp = (const float4*)(x + (size_t)n * 32);
#pragma unroll
    for (int j = 0; j < 8; j++) {
        float4 t = xp[j];
        xv[4*j] = t.x; xv[4*j+1] = t.y; xv[4*j+2] = t.z; xv[4*j+3] = t.w;
    }
    u64 acc[16];
#pragma unroll
    for (int m = 0; m < 16; m++) acc[m] = pack2(0.f, 0.f);
#pragma unroll
    for (int f = 0; f < 32; f++) {
        u64 xf = pack2(xv[f], xv[f]);
        const ulonglong2* rp = (const ulonglong2*)(Rs + f * 32);
#pragma unroll
        for (int j = 0; j < 8; j++) {
            ulonglong2 w = rp[j];
            acc[2*j]   = fma2(xf, w.x, acc[2*j]);
            acc[2*j+1] = fma2(xf, w.y, acc[2*j+1]);
        }
    }
    float xr[32];
#pragma unroll
    for (int m = 0; m < 16; m++) unpack2(acc[m], xr[2*m], xr[2*m+1]);

    float rd = 0.f;
#pragma unroll
    for (int o = 0; o < 32; o++) rd += xr[o] * a1s[o];
    g_rdot[n]  = rd;
    g_denom[n] = 0.f;

    float4* xrbp = (float4*)(g_xrb + (size_t)n * 32);
    float4* accp = (float4*)(g_acc + (size_t)n * 32);
#pragma unroll
    for (int j = 0; j < 8; j++) {
        float4 v;
        v.x = xr[4*j]   + bsh[4*j];
        v.y = xr[4*j+1] + bsh[4*j+1];
        v.z = xr[4*j+2] + bsh[4*j+2];
        v.w = xr[4*j+3] + bsh[4*j+3];
        xrbp[j] = v;
        accp[j] = make_float4(0.f, 0.f, 0.f, 0.f);
    }
}

// ---------------------------------------------------------------------------
// K2 (chunked): xw[n-c0,k,:] = fp16( x[n,:] @ W[k] ) for n in [c0, c0+CHN)
//   64-thread blocks so a 25k chunk still makes 391 blocks (fills the chip)
// ---------------------------------------------------------------------------
__global__ __launch_bounds__(64) void k2_xw(
    const float* __restrict__ x, const float* __restrict__ W, int c0)
{
    __shared__ __align__(16) float Ws[1024];
    int tid = threadIdx.x;
    int l = blockIdx.x * 64 + tid;          // local node index in chunk
    bool act = (l < CHN);
    int n = c0 + l;

    float xv[32];
    if (act) {
        const float4* xp = (const float4*)(x + (size_t)n * 32);
#pragma unroll
        for (int j = 0; j < 8; j++) {
            float4 t = xp[j];
            xv[4*j] = t.x; xv[4*j+1] = t.y; xv[4*j+2] = t.z; xv[4*j+3] = t.w;
        }
    }
    uint4* outp = ((uint4*)g_xwh) + (size_t)l * 100;

#pragma unroll 1
    for (int k = 0; k < 25; k++) {
        __syncthreads();
#pragma unroll
        for (int i = 0; i < 4; i++)
            ((float4*)Ws)[tid + 64 * i] = ((const float4*)(W + k * 1024))[tid + 64 * i];
        __syncthreads();
        if (act) {
            u64 acc[16];
#pragma unroll
            for (int m = 0; m < 16; m++) acc[m] = pack2(0.f, 0.f);
#pragma unroll
            for (int f = 0; f < 32; f++) {
                u64 xf = pack2(xv[f], xv[f]);
                const ulonglong2* rp = (const ulonglong2*)(Ws + f * 32);
#pragma unroll
                for (int j = 0; j < 8; j++) {
                    ulonglong2 w = rp[j];
                    acc[2*j]   = fma2(xf, w.x, acc[2*j]);
                    acc[2*j+1] = fma2(xf, w.y, acc[2*j+1]);
                }
            }
#pragma unroll
            for (int j = 0; j < 4; j++) {
                uint4 v;
                v.x = h2bits(acc[4*j]);
                v.y = h2bits(acc[4*j+1]);
                v.z = h2bits(acc[4*j+2]);
                v.w = h2bits(acc[4*j+3]);
                outp[k * 4 + j] = v;
            }
        }
    }
}

// ---------------------------------------------------------------------------
// K3 (pass): full edge scan; serve edges whose col is in [c0, c0+CHN).
//   8 lanes/edge; gather hits the L2-hot xw chunk just written by K2.
//   8-lane edge groups diverge together; shfl uses group-local masks.
// ---------------------------------------------------------------------------
__global__ __launch_bounds__(256) void k3_edge(
    const int* __restrict__ ei, const float* __restrict__ pseudo,
    const float* __restrict__ attW, int c0)
{
    int t = blockIdx.x * 256 + threadIdx.x;
    int e   = t >> 3;
    int sub = t & 7;

    int col = __ldg(ei + NE + e);
    unsigned cl = (unsigned)(col - c0);
    if (cl < CHN) {
        int row = __ldg(ei + e);
        float p0 = __ldg(pseudo + 2 * e)     * 4.f;
        float p1 = __ldg(pseudo + 2 * e + 1) * 4.f;
        float fl0 = floorf(p0), fl1 = floorf(p1);
        float fr0 = p0 - fl0,   fr1 = p1 - fl1;
        int i0 = (int)fl0, i1 = (int)fl1;     // always <= 3 (pseudo in [0,1))

        const uint2* base = g_xwh + (size_t)cl * 200 + sub;
        float m0 = 0.f, m1 = 0.f, m2 = 0.f, m3 = 0.f;
#pragma unroll
        for (int s = 0; s < 4; s++) {
            int o0 = s & 1, o1 = (s >> 1) & 1;
            float b = (o0 ? fr0 : 1.f - fr0) * (o1 ? fr1 : 1.f - fr1);
            int w = (i0 + o0) + 5 * (i1 + o1);
            uint2 v = __ldg(base + w * 8);
            float2 f0 = __half22float2(*reinterpret_cast<const __half2*>(&v.x));
            float2 f1 = __half22float2(*reinterpret_cast<const __half2*>(&v.y));
            m0 = fmaf(b, f0.x, m0); m1 = fmaf(b, f0.y, m1);
            m2 = fmaf(b, f1.x, m2); m3 = fmaf(b, f1.y, m3);
        }

        float4 a2 = __ldg(((const float4*)(attW + 32)) + sub);
        float d = m0 * a2.x + m1 * a2.y + m2 * a2.z + m3 * a2.w;
        unsigned gm = 0xFFu << (threadIdx.x & 24);   // 8-lane group mask
        d += __shfl_xor_sync(gm, d, 1);
        d += __shfl_xor_sync(gm, d, 2);
        d += __shfl_xor_sync(gm, d, 4);

        float alpha = d + __ldg(g_rdot + row);
        alpha = (alpha > 0.f) ? alpha : 0.2f * alpha;    // leaky relu
        float ex = __expf(alpha);      // softmax max-shift cancels in the ratio

        if (sub == 0) atomicAdd(g_denom + row, ex);

        float* ap = g_acc + (size_t)row * 32 + sub * 4;
        asm volatile("red.global.add.v4.f32 [%0], {%1,%2,%3,%4};"
                     :: "l"(ap), "f"(m0 * ex), "f"(m1 * ex),
                        "f"(m2 * ex), "f"(m3 * ex)
                     : "memory");
    }
}

// ---------------------------------------------------------------------------
// K4: out = acc / (denom + 1e-16) + (x_root + bias)
// ---------------------------------------------------------------------------
__global__ __launch_bounds__(256) void k4_out(float* __restrict__ out)
{
    int i = blockIdx.x * 256 + threadIdx.x;
    int n = i >> 3;
    float r = 1.f / (g_denom[n] + 1e-16f);
    float4 a  = ((const float4*)g_acc)[i];
    float4 xr = ((const float4*)g_xrb)[i];
    float4 o;
    o.x = fmaf(a.x, r, xr.x);
    o.y = fmaf(a.y, r, xr.y);
    o.z = fmaf(a.z, r, xr.z);
    o.w = fmaf(a.w, r, xr.w);
    ((float4*)out)[i] = o;
}

extern "C" void kernel_launch(void* const* d_in, const int* in_sizes, int n_in,
                              void* d_out, int out_size)
{
    const float* x      = (const float*)d_in[0];
    const int*   ei     = (const int*)d_in[1];
    const float* pseudo = (const float*)d_in[2];
    const float* W      = (const float*)d_in[3];
    const float* rootW  = (const float*)d_in[4];
    const float* attW   = (const float*)d_in[5];
    const float* bias   = (const float*)d_in[6];
    float* out = (float*)d_out;

    k1_node<<<(NN + 255) / 256, 256>>>(x, rootW, attW, bias);
    for (int c = 0; c < NCHUNK; c++) {
        int c0 = c * CHN;
        k2_xw  <<<(CHN + 63) / 64, 64>>>(x, W, c0);
        k3_edge<<<(NE * 8) / 256, 256>>>(ei, pseudo, attW, c0);
    }
    k4_out <<<(NN * 32 / 4) / 256, 256>>>(out);
}

// round 5
// speedup vs baseline: 2.2823x; 2.2823x over previous
#include <cuda_runtime.h>
#include <cuda_fp16.h>
#include <mma.h>
using namespace nvcuda;

#define NN 100000
#define NNP 100032          // padded to 64-node k2 blocks
#define NE 1600000

// fp16 copies of x and W for tensor-core k2
__device__ __half g_xh[(size_t)NNP * 32];
__device__ __half g_wh[25 * 32 * 32];
// xw in fp16: [NNP][25 kernels][32 feats] = 1600B/node
__device__ uint2 g_xwh[(size_t)NNP * 200];
__device__ float g_acc[(size_t)NN * 32];
__device__ float g_xrb[(size_t)NN * 32];
__device__ float g_rdot[NN];
__device__ float g_denom[NN];

typedef unsigned long long u64;

__device__ __forceinline__ u64 pack2(float a, float b) {
    u64 r; asm("mov.b64 %0,{%1,%2};" : "=l"(r) : "f"(a), "f"(b)); return r;
}
__device__ __forceinline__ void unpack2(u64 v, float& a, float& b) {
    asm("mov.b64 {%0,%1},%2;" : "=f"(a), "=f"(b) : "l"(v));
}
__device__ __forceinline__ u64 fma2(u64 a, u64 b, u64 c) {
    u64 d; asm("fma.rn.f32x2 %0,%1,%2,%3;" : "=l"(d) : "l"(a), "l"(b), "l"(c)); return d;
}
// two fp32 -> packed half2 bits (round-to-nearest)
__device__ __forceinline__ unsigned h2b(float a, float b) {
    unsigned r; asm("cvt.rn.f16x2.f32 %0,%2,%1;" : "=r"(r) : "f"(a), "f"(b));
    return r;   // low half = a
}

// ---------------------------------------------------------------------------
// K0: convert W (25*32*32 fp32) to fp16
// ---------------------------------------------------------------------------
__global__ __launch_bounds__(256) void k0_wh(const float* __restrict__ W)
{
    int i = blockIdx.x * 256 + threadIdx.x;     // 12800 half2 slots
    float2 v = ((const float2*)W)[i];
    ((unsigned*)g_wh)[i] = h2b(v.x, v.y);
}

// ---------------------------------------------------------------------------
// K1: root transform + attention dot + zero-init + x->fp16 copy
// ---------------------------------------------------------------------------
__global__ __launch_bounds__(256) void k1_node(
    const float* __restrict__ x, const float* __restrict__ rootW,
    const float* __restrict__ attW, const float* __restrict__ bias)
{
    __shared__ __align__(16) float Rs[1024];
    __shared__ float a1s[32], bsh[32];
    int tid = threadIdx.x;
    ((float4*)Rs)[tid] = ((const float4*)rootW)[tid];
    if (tid < 32) { a1s[tid] = attW[tid]; bsh[tid] = bias[tid]; }
    __syncthreads();

    int n = blockIdx.x * 256 + tid;
    if (n >= NN) return;

    float xv[32];
    const float4* xp = (const float4*)(x + (size_t)n * 32);
#pragma unroll
    for (int j = 0; j < 8; j++) {
        float4 t = xp[j];
        xv[4*j] = t.x; xv[4*j+1] = t.y; xv[4*j+2] = t.z; xv[4*j+3] = t.w;
    }
    // fp16 copy of x for k2
    uint4* xhp = ((uint4*)g_xh) + (size_t)n * 4;
#pragma unroll
    for (int j = 0; j < 4; j++) {
        uint4 h;
        h.x = h2b(xv[8*j],   xv[8*j+1]);
        h.y = h2b(xv[8*j+2], xv[8*j+3]);
        h.z = h2b(xv[8*j+4], xv[8*j+5]);
        h.w = h2b(xv[8*j+6], xv[8*j+7]);
        xhp[j] = h;
    }

    u64 acc[16];
#pragma unroll
    for (int m = 0; m < 16; m++) acc[m] = pack2(0.f, 0.f);
#pragma unroll
    for (int f = 0; f < 32; f++) {
        u64 xf = pack2(xv[f], xv[f]);
        const ulonglong2* rp = (const ulonglong2*)(Rs + f * 32);
#pragma unroll
        for (int j = 0; j < 8; j++) {
            ulonglong2 w = rp[j];
            acc[2*j]   = fma2(xf, w.x, acc[2*j]);
            acc[2*j+1] = fma2(xf, w.y, acc[2*j+1]);
        }
    }
    float xr[32];
#pragma unroll
    for (int m = 0; m < 16; m++) unpack2(acc[m], xr[2*m], xr[2*m+1]);

    float rd = 0.f;
#pragma unroll
    for (int o = 0; o < 32; o++) rd += xr[o] * a1s[o];
    g_rdot[n]  = rd;
    g_denom[n] = 0.f;

    float4* xrbp = (float4*)(g_xrb + (size_t)n * 32);
    float4* accp = (float4*)(g_acc + (size_t)n * 32);
#pragma unroll
    for (int j = 0; j < 8; j++) {
        float4 v;
        v.x = xr[4*j]   + bsh[4*j];
        v.y = xr[4*j+1] + bsh[4*j+1];
        v.z = xr[4*j+2] + bsh[4*j+2];
        v.w = xr[4*j+3] + bsh[4*j+3];
        xrbp[j] = v;
        accp[j] = make_float4(0.f, 0.f, 0.f, 0.f);
    }
}

// ---------------------------------------------------------------------------
// K2: tensor-core xw. 8 warps/block, 64 nodes/block.
//   Warp (mtile = w&3, ntile = w>>2) computes [16 nodes x 16 feats] per kernel.
//   A frags loaded once (reused over 25 kernels); B streamed from L1-hot W_h.
// ---------------------------------------------------------------------------
__global__ __launch_bounds__(256) void k2_wmma()
{
    __shared__ __align__(16) float stag[8 * 256];
    int warp = threadIdx.x >> 5, lane = threadIdx.x & 31;
    int mtile = warp & 3, ntile = warp >> 2;
    int m0 = blockIdx.x * 64 + mtile * 16;       // node base (padded, < NNP)

    wmma::fragment<wmma::matrix_a, 16, 16, 16, __half, wmma::row_major> a0, a1;
    wmma::load_matrix_sync(a0, g_xh + (size_t)m0 * 32,      32);
    wmma::load_matrix_sync(a1, g_xh + (size_t)m0 * 32 + 16, 32);

    float* sw = stag + warp * 256;
    int r = lane >> 1, h = lane & 1;
    const float* sp = sw + r * 16 + h * 8;
    uint4* outp = ((uint4*)g_xwh) + (size_t)(m0 + r) * 100 + ntile * 2 + h;

#pragma unroll 1
    for (int k = 0; k < 25; k++) {
        wmma::fragment<wmma::matrix_b, 16, 16, 16, __half, wmma::row_major> b;
        wmma::fragment<wmma::accumulator, 16, 16, 16, float> c;
        wmma::fill_fragment(c, 0.f);
        wmma::load_matrix_sync(b, g_wh + k * 1024 + ntile * 16, 32);
        wmma::mma_sync(c, a0, b, c);
        wmma::load_matrix_sync(b, g_wh + k * 1024 + 512 + ntile * 16, 32);
        wmma::mma_sync(c, a1, b, c);
        wmma::store_matrix_sync(sw, c, 16, wmma::mem_row_major);
        __syncwarp();
        uint4 v;
        v.x = h2b(sp[0], sp[1]);
        v.y = h2b(sp[2], sp[3]);
        v.z = h2b(sp[4], sp[5]);
        v.w = h2b(sp[6], sp[7]);
        outp[k * 4] = v;
        __syncwarp();
    }
}

// ---------------------------------------------------------------------------
// K3: single edge pass, 8 lanes/edge, fp16 gather (round-3 shape).
// ---------------------------------------------------------------------------
__global__ __launch_bounds__(256) void k3_edge(
    const int* __restrict__ ei, const float* __restrict__ pseudo,
    const float* __restrict__ attW)
{
    int t = blockIdx.x * 256 + threadIdx.x;
    int e   = t >> 3;
    int sub = t & 7;

    int row = __ldg(ei + e);
    int col = __ldg(ei + NE + e);
    float p0 = __ldg(pseudo + 2 * e)     * 4.f;
    float p1 = __ldg(pseudo + 2 * e + 1) * 4.f;
    float fl0 = floorf(p0), fl1 = floorf(p1);
    float fr0 = p0 - fl0,   fr1 = p1 - fl1;
    int i0 = (int)fl0, i1 = (int)fl1;           // <= 3 always

    const uint2* base = g_xwh + (size_t)col * 200 + sub;
    float m0 = 0.f, m1 = 0.f, m2 = 0.f, m3 = 0.f;
#pragma unroll
    for (int s = 0; s < 4; s++) {
        int o0 = s & 1, o1 = (s >> 1) & 1;
        float b = (o0 ? fr0 : 1.f - fr0) * (o1 ? fr1 : 1.f - fr1);
        int w = (i0 + o0) + 5 * (i1 + o1);
        uint2 v = __ldg(base + w * 8);
        float2 f0 = __half22float2(*reinterpret_cast<const __half2*>(&v.x));
        float2 f1 = __half22float2(*reinterpret_cast<const __half2*>(&v.y));
        m0 = fmaf(b, f0.x, m0); m1 = fmaf(b, f0.y, m1);
        m2 = fmaf(b, f1.x, m2); m3 = fmaf(b, f1.y, m3);
    }

    float4 a2 = __ldg(((const float4*)(attW + 32)) + sub);
    float d = m0 * a2.x + m1 * a2.y + m2 * a2.z + m3 * a2.w;
    d += __shfl_xor_sync(0xffffffffu, d, 1);
    d += __shfl_xor_sync(0xffffffffu, d, 2);
    d += __shfl_xor_sync(0xffffffffu, d, 4);

    float alpha = d + __ldg(g_rdot + row);
    alpha = (alpha > 0.f) ? alpha : 0.2f * alpha;     // leaky relu
    float ex = __expf(alpha);        // softmax max-shift cancels in the ratio

    if (sub == 0) atomicAdd(g_denom + row, ex);

    float* ap = g_acc + (size_t)row * 32 + sub * 4;
    asm volatile("red.global.add.v4.f32 [%0], {%1,%2,%3,%4};"
                 :: "l"(ap), "f"(m0 * ex), "f"(m1 * ex),
                    "f"(m2 * ex), "f"(m3 * ex)
                 : "memory");
}

// ---------------------------------------------------------------------------
// K4: out = acc / (denom + 1e-16) + (x_root + bias)
// ---------------------------------------------------------------------------
__global__ __launch_bounds__(256) void k4_out(float* __restrict__ out)
{
    int i = blockIdx.x * 256 + threadIdx.x;
    int n = i >> 3;
    float r = 1.f / (g_denom[n] + 1e-16f);
    float4 a  = ((const float4*)g_acc)[i];
    float4 xr = ((const float4*)g_xrb)[i];
    float4 o;
    o.x = fmaf(a.x, r, xr.x);
    o.y = fmaf(a.y, r, xr.y);
    o.z = fmaf(a.z, r, xr.z);
    o.w = fmaf(a.w, r, xr.w);
    ((float4*)out)[i] = o;
}

extern "C" void kernel_launch(void* const* d_in, const int* in_sizes, int n_in,
                              void* d_out, int out_size)
{
    const float* x      = (const float*)d_in[0];
    const int*   ei     = (const int*)d_in[1];
    const float* pseudo = (const float*)d_in[2];
    const float* W      = (const float*)d_in[3];
    const float* rootW  = (const float*)d_in[4];
    const float* attW   = (const float*)d_in[5];
    const float* bias   = (const float*)d_in[6];
    float* out = (float*)d_out;

    k0_wh  <<<50, 256>>>(W);                         // 12800 half2
    k1_node<<<(NN + 255) / 256, 256>>>(x, rootW, attW, bias);
    k2_wmma<<<NNP / 64, 256>>>();
    k3_edge<<<(NE * 8) / 256, 256>>>(ei, pseudo, attW);
    k4_out <<<(NN * 32 / 4) / 256, 256>>>(out);
}